// round 9
// baseline (speedup 1.0000x reference)
#include <cuda_runtime.h>
#include <cstdint>

// Problem constants (fixed for rotary_13872744366393):
//   x: (4, 8192, 1024) f32, matrix: (64,64), thetas: (32), tscale: (1),
//   invf: (32), pairs: (32,2) int32. out: (4, 8192, 1024) f32.
#define HEADS 16
#define D     64
#define ROTN  32
#define SEQ   8192

typedef unsigned long long u64;

// B = M packed for the mainloop: g_Bp[h][kk][c] = (M[2kk][8h+c], M[2kk+1][8h+c])
// padded to 258 u64 per colg block (2064 B) for conflict-free smem LDS.128.
#define B_BLK_U64 258
__device__ u64 g_Bp[8 * B_BLK_U64];

// packed f32x2 FMA (Blackwell): d = a*b + d
#define FMA2(d, a, b) \
    asm("fma.rn.f32x2 %0, %1, %2, %0;" : "+l"(d) : "l"(a), "l"(b))

// 8-byte async copy global->shared (LDGSTS)
#define CP_ASYNC8(dst_u32, src_ptr) \
    asm volatile("{ .reg .u64 g; cvta.to.global.u64 g, %1; " \
                 "cp.async.ca.shared.global [%0], [g], 8; }" \
                 :: "r"(dst_u32), "l"(src_ptr) : "memory")
#define CP_COMMIT() asm volatile("cp.async.commit_group;" ::: "memory")
#define CP_WAIT0()  asm volatile("cp.async.wait_group 0;" ::: "memory")

__device__ __forceinline__ uint32_t smem_u32(const void* p) {
    uint32_t a;
    asm("{ .reg .u64 t; cvta.to.shared.u64 t, %1; cvt.u32.u64 %0, t; }"
        : "=r"(a) : "l"(p));
    return a;
}

// ---------------------------------------------------------------------------
// Kernel 1: build M = G_comb @ matrix, emit packed B.
// G_comb = I @ G_0 @ ... @ G_31 ; right-multiplying by G_q updates COLUMNS:
//   col_i' = col_i*c + col_j*s ;  col_j' = -col_i*s + col_j*c
// Degenerate i==j (JAX .at sequence leaves G[i,i] = sin): col_i' = col_i*s
// ---------------------------------------------------------------------------
__global__ void build_M_kernel(const float* __restrict__ matrix,
                               const float* __restrict__ thetas,
                               const float* __restrict__ tscale,
                               const int*   __restrict__ pairs) {
    __shared__ float Gs[64][65];
    __shared__ float Mat[64][64];
    __shared__ float Msh[64][64];
    __shared__ float ssin[ROTN], scos[ROTN];
    __shared__ int   sij[ROTN][2];
    const int tid = threadIdx.x;   // 256 threads

    for (int i = tid; i < 64 * 64; i += 256)
        Mat[i >> 6][i & 63] = matrix[i];

    if (tid < ROTN) {                      // sincos once, not per-row
        const float th = thetas[tid] * tscale[0];
        float s, c;
        sincosf(th, &s, &c);
        ssin[tid] = s;
        scos[tid] = c;
        sij[tid][0] = pairs[2 * tid];
        sij[tid][1] = pairs[2 * tid + 1];
    }
    if (tid < 64) {
        #pragma unroll
        for (int k = 0; k < 64; k++) Gs[tid][k] = (tid == k) ? 1.0f : 0.0f;
    }
    __syncthreads();

    if (tid < 64) {
        for (int q = 0; q < ROTN; q++) {
            const int   i = sij[q][0];
            const int   j = sij[q][1];
            const float s = ssin[q];
            const float c = scos[q];
            const float ai = Gs[tid][i];
            const float aj = Gs[tid][j];
            if (i != j) {
                Gs[tid][i] = ai * c + aj * s;
                Gs[tid][j] = -ai * s + aj * c;
            } else {
                Gs[tid][i] = ai * s;
            }
        }
    }
    __syncthreads();

    {
        const int r  = tid >> 2;
        const int qq = tid & 3;
        float gr[64];
        #pragma unroll
        for (int k = 0; k < 64; k++) gr[k] = Gs[r][k];
        #pragma unroll
        for (int n0 = 0; n0 < 16; n0++) {
            const int n = qq * 16 + n0;
            float acc = 0.0f;
            #pragma unroll
            for (int k = 0; k < 64; k++) acc = fmaf(gr[k], Mat[k][n], acc);
            Msh[r][n] = acc;
        }
    }
    __syncthreads();

    // pack: g_Bp[h*258 + kk*8 + c] = (M[2kk][8h+c], M[2kk+1][8h+c])
    for (int idx = tid; idx < 8 * 32 * 8; idx += 256) {
        const int h  = idx >> 8;
        const int kk = (idx >> 3) & 31;
        const int c  = idx & 7;
        const int n  = 8 * h + c;
        float2 p = make_float2(Msh[2 * kk][n], Msh[2 * kk + 1][n]);
        g_Bp[h * B_BLK_U64 + kk * 8 + c] = *(const u64*)&p;
    }
}

// ---------------------------------------------------------------------------
// Kernel 2: PERSISTENT register-tiled f32x2 GEMM (8x8 per thread) + RoPE.
// 296 CTAs x 128 threads, each CTA loops over tiles of 128 rows with
// double-buffered A (cp.async, no staging registers) and double-buffered
// sincos table. B staged to smem once per CTA.
// Thread (w,g,h): rows R(r) = w*8 + g*2 + (r&1) + (r>>1)*32, cols 8h..8h+7.
// A K-MAJOR: plane stride 1040 B (16B-aligned); rows (R,R+1) 16B-adjacent
// => 4x LDS.128 per kk. B per-colg blocks of 2064 B => 4x LDS.128.
// ---------------------------------------------------------------------------
#define A_K_STRIDE 1040
#define A_BUF_SZ   (32 * A_K_STRIDE)              // 33280
#define SM_A0    0
#define SM_A1    A_BUF_SZ                         // 33280
#define SM_B     (2 * A_BUF_SZ)                   // 66560
#define SM_SC0   (SM_B + 8 * B_BLK_U64 * 8)       // 66560 + 16512 = 83072
#define SM_SC1   (SM_SC0 + 2048)                  // 85120
#define SMEM_DYN (SM_SC1 + 2048)                  // 87168

#define GRID_PERSIST 296

__global__ __launch_bounds__(128, 2)
void rotary_f2(const float* __restrict__ x,
               const float* __restrict__ invf,
               float* __restrict__ out,
               int ntiles) {
    extern __shared__ __align__(16) char dsm[];

    const int tid  = threadIdx.x;
    const int w    = tid >> 5;
    const int lane = tid & 31;
    const int g    = lane >> 3;     // row group 0..3
    const int h    = lane & 7;      // col group 0..7

    const uint32_t smbase = smem_u32(dsm);
    const uint32_t abuf_u32[2] = {smbase + SM_A0, smbase + SM_A1};
    float2* scbuf[2] = {(float2*)(dsm + SM_SC0), (float2*)(dsm + SM_SC1)};

    // ---- B once per CTA ----
    {
        u64* bs = (u64*)(dsm + SM_B);
        #pragma unroll
        for (int i = 0; i < 17; i++) {
            const int idx = tid + 128 * i;
            if (idx < 8 * B_BLK_U64) bs[idx] = g_Bp[idx];
        }
    }

    // ---- staging helpers (inlined via lambdas) ----
    auto stage_A = [&](int T, uint32_t abase_u32) {
        const u64* xs = (const u64*)(x + (size_t)T * 128 * 64);  // 2048 u64
        #pragma unroll
        for (int i = 0; i < 16; i++) {
            const int idx = i * 128 + tid;        // 16B chunk id
            const int row = idx >> 4;
            const int kq  = idx & 15;
            const uint32_t d0 = abase_u32 + row * 8 + (2 * kq) * A_K_STRIDE;
            CP_ASYNC8(d0,              xs + 2 * idx);
            CP_ASYNC8(d0 + A_K_STRIDE, xs + 2 * idx + 1);
        }
    };
    auto stage_sc = [&](int T, float2* sct) {
        #pragma unroll
        for (int e = 0; e < 2; e++) {
            const int idx = tid * 2 + e;          // 256 entries
            const int t = idx >> 5, m = idx & 31;
            const int pos = (T * 8 + t) & (SEQ - 1);
            float sn, cs;
            sincosf((float)pos * invf[m], &sn, &cs);
            sct[idx] = make_float2(sn, cs);
        }
    };

    // ---- prologue: stage tile T0 into buffer 0 ----
    int T = blockIdx.x;
    if (T < ntiles) {
        stage_A(T, abuf_u32[0]);
        stage_sc(T, scbuf[0]);
    }
    CP_COMMIT();
    CP_WAIT0();
    __syncthreads();

    const int rowbase = w * 8 + g * 2;
    int buf = 0;

    for (; T < ntiles; T += GRID_PERSIST) {
        // prefetch next tile into the other buffer
        const int Tn = T + GRID_PERSIST;
        if (Tn < ntiles) {
            stage_A(Tn, abuf_u32[buf ^ 1]);
            stage_sc(Tn, scbuf[buf ^ 1]);
        }
        CP_COMMIT();

        // ---- mainloop on buf ----
        const char* abase = dsm + (buf ? SM_A1 : SM_A0) + rowbase * 8;
        const char* bbase = dsm + SM_B + h * (B_BLK_U64 * 8);

        u64 acc[64];
        #pragma unroll
        for (int i = 0; i < 64; i++) acc[i] = 0ull;

        u64 au[2][8], bu[2][8];
        #pragma unroll
        for (int j = 0; j < 4; j++) {
            const ulonglong2 a2 = *(const ulonglong2*)(abase + j * 256);
            au[0][2 * j] = a2.x;  au[0][2 * j + 1] = a2.y;
            const ulonglong2 b2 = *(const ulonglong2*)(bbase + j * 16);
            bu[0][2 * j] = b2.x;  bu[0][2 * j + 1] = b2.y;
        }

        #pragma unroll 4
        for (int kk = 0; kk < 32; kk++) {
            const int cur = kk & 1, nxt = cur ^ 1;
            if (kk < 31) {
                const char* ap = abase + (kk + 1) * A_K_STRIDE;
                const char* bp = bbase + (kk + 1) * 64;
                #pragma unroll
                for (int j = 0; j < 4; j++) {
                    const ulonglong2 a2 = *(const ulonglong2*)(ap + j * 256);
                    au[nxt][2 * j] = a2.x;  au[nxt][2 * j + 1] = a2.y;
                    const ulonglong2 b2 = *(const ulonglong2*)(bp + j * 16);
                    bu[nxt][2 * j] = b2.x;  bu[nxt][2 * j + 1] = b2.y;
                }
            }
            #pragma unroll
            for (int r = 0; r < 8; r++) {
                #pragma unroll
                for (int c = 0; c < 8; c++) {
                    FMA2(acc[r * 8 + c], au[cur][r], bu[cur][c]);
                }
            }
        }

        // ---- epilogue: hsum, RoPE, *sqrt(1024)=32, STG ----
        const float2* sct = scbuf[buf];
        #pragma unroll
        for (int r = 0; r < 8; r++) {
            const int row = rowbase + (r & 1) + (r >> 1) * 32;
            const int tok = row >> 4;
            float o1[4], o2[4];
            #pragma unroll
            for (int p = 0; p < 4; p++) {
                const float2 scm = sct[tok * 32 + 4 * h + p];
                const float2 a0 = *(const float2*)&acc[r * 8 + 2 * p];
                const float2 a1 = *(const float2*)&acc[r * 8 + 2 * p + 1];
                const float y1 = a0.x + a0.y;
                const float y2 = a1.x + a1.y;
                o1[p] = (y1 * scm.y - y2 * scm.x) * 32.0f;
                o2[p] = (y1 * scm.x + y2 * scm.y) * 32.0f;
            }
            float* orow = out + ((size_t)T * 128 + row) * 64;
            *(float4*)(orow + 4 * h)      = make_float4(o1[0], o1[1], o1[2], o1[3]);
            *(float4*)(orow + 32 + 4 * h) = make_float4(o2[0], o2[1], o2[2], o2[3]);
        }

        CP_WAIT0();
        __syncthreads();
        buf ^= 1;
    }
}

// ---------------------------------------------------------------------------
extern "C" void kernel_launch(void* const* d_in, const int* in_sizes, int n_in,
                              void* d_out, int out_size) {
    const float* x      = (const float*)d_in[0];
    const float* matrix = (const float*)d_in[1];
    const float* thetas = (const float*)d_in[2];
    const float* tscale = (const float*)d_in[3];
    const float* invf   = (const float*)d_in[4];
    const int*   pairs  = (const int*)d_in[5];
    float* out = (float*)d_out;

    static bool attr_set = false;
    if (!attr_set) {
        cudaFuncSetAttribute(rotary_f2,
                             cudaFuncAttributeMaxDynamicSharedMemorySize,
                             SMEM_DYN);
        attr_set = true;
    }

    const int nrows  = in_sizes[0] / D;      // 524288
    const int ntiles = nrows / 128;          // 4096

    build_M_kernel<<<1, 256>>>(matrix, thetas, tscale, pairs);
    rotary_f2<<<GRID_PERSIST, 128, SMEM_DYN>>>(x, invf, out, ntiles);
}

// round 10
// speedup vs baseline: 1.1153x; 1.1153x over previous
#include <cuda_runtime.h>
#include <cstdint>

// Problem constants (fixed for rotary_13872744366393):
//   x: (4, 8192, 1024) f32, matrix: (64,64), thetas: (32), tscale: (1),
//   invf: (32), pairs: (32,2) int32. out: (4, 8192, 1024) f32.
#define HEADS 16
#define D     64
#define ROTN  32
#define SEQ   8192

typedef unsigned long long u64;

// B = M packed for the mainloop: g_Bp[h][kk][c] = (M[2kk][8h+c], M[2kk+1][8h+c])
// padded to 258 u64 per colg block (2064 B) for conflict-free smem LDS.128.
#define B_BLK_U64 258
__device__ u64 g_Bp[8 * B_BLK_U64];

// packed f32x2 FMA (Blackwell): d = a*b + d
#define FMA2(d, a, b) \
    asm("fma.rn.f32x2 %0, %1, %2, %0;" : "+l"(d) : "l"(a), "l"(b))

// ---------------------------------------------------------------------------
// Kernel 1: build M = G_comb @ matrix, emit packed B.
// G_comb = I @ G_0 @ ... @ G_31 ; right-multiplying by G_q updates COLUMNS:
//   col_i' = col_i*c + col_j*s ;  col_j' = -col_i*s + col_j*c
// Degenerate i==j (JAX .at sequence leaves G[i,i] = sin): col_i' = col_i*s
// ---------------------------------------------------------------------------
__global__ void build_M_kernel(const float* __restrict__ matrix,
                               const float* __restrict__ thetas,
                               const float* __restrict__ tscale,
                               const int*   __restrict__ pairs) {
    __shared__ float Gs[64][65];
    __shared__ float Mat[64][64];
    __shared__ float Msh[64][64];
    __shared__ float ssin[ROTN], scos[ROTN];
    __shared__ int   sij[ROTN][2];
    const int tid = threadIdx.x;   // 256 threads

    for (int i = tid; i < 64 * 64; i += 256)
        Mat[i >> 6][i & 63] = matrix[i];

    if (tid < ROTN) {                      // sincos once, not per-row
        const float th = thetas[tid] * tscale[0];
        float s, c;
        sincosf(th, &s, &c);
        ssin[tid] = s;
        scos[tid] = c;
        sij[tid][0] = pairs[2 * tid];
        sij[tid][1] = pairs[2 * tid + 1];
    }
    if (tid < 64) {
        #pragma unroll
        for (int k = 0; k < 64; k++) Gs[tid][k] = (tid == k) ? 1.0f : 0.0f;
    }
    __syncthreads();

    if (tid < 64) {
        for (int q = 0; q < ROTN; q++) {
            const int   i = sij[q][0];
            const int   j = sij[q][1];
            const float s = ssin[q];
            const float c = scos[q];
            const float ai = Gs[tid][i];
            const float aj = Gs[tid][j];
            if (i != j) {
                Gs[tid][i] = ai * c + aj * s;
                Gs[tid][j] = -ai * s + aj * c;
            } else {
                Gs[tid][i] = ai * s;
            }
        }
    }
    __syncthreads();

    {
        const int r  = tid >> 2;
        const int qq = tid & 3;
        float gr[64];
        #pragma unroll
        for (int k = 0; k < 64; k++) gr[k] = Gs[r][k];
        #pragma unroll
        for (int n0 = 0; n0 < 16; n0++) {
            const int n = qq * 16 + n0;
            float acc = 0.0f;
            #pragma unroll
            for (int k = 0; k < 64; k++) acc = fmaf(gr[k], Mat[k][n], acc);
            Msh[r][n] = acc;
        }
    }
    __syncthreads();

    // pack: g_Bp[h*258 + kk*8 + c] = (M[2kk][8h+c], M[2kk+1][8h+c])
    for (int idx = tid; idx < 8 * 32 * 8; idx += 256) {
        const int h  = idx >> 8;
        const int kk = (idx >> 3) & 31;
        const int c  = idx & 7;
        const int n  = 8 * h + c;
        float2 p = make_float2(Msh[2 * kk][n], Msh[2 * kk + 1][n]);
        g_Bp[h * B_BLK_U64 + kk * 8 + c] = *(const u64*)&p;
    }
}

// ---------------------------------------------------------------------------
// Kernel 2: register-tiled f32x2 GEMM (8 rows x 8 cols per thread) + RoPE.
// CTA = 128 threads, 128 rows, grid 4096. lane = rowg(g) x colg(h):
//   rows  R(r) = w*8 + g*2 + (r&1) + (r>>1)*32,  r = 0..7
//   cols  8h .. 8h+7
// A stored K-MAJOR, plane stride 1040 B (16B-aligned): rows (R, R+1) are
// 16B-adjacent => 4x LDS.128 per kk; g-lanes at +16B (4 banks), h-lanes
// broadcast. B per-colg blocks (2064 B): 4x LDS.128, conflict-free.
// __launch_bounds__(128, 3): 12 warps/SM (3/SMSP) for cross-warp latency
// cover; no explicit double-buffer (won't fit 170 regs) — the kk loop is
// FULLY unrolled so every LDS offset is an immediate (zero loop IMADs) and
// ptxas hoists loads freely within the register budget.
// ---------------------------------------------------------------------------
#define A_K_STRIDE 1040
#define SM_A     0
#define SM_B     (32 * A_K_STRIDE)                // 33280
#define SM_SC    (SM_B + 8 * B_BLK_U64 * 8)       // 33280 + 16512 = 49792
#define SMEM_DYN (SM_SC + 8 * 32 * 8)             // + 2048 = 51840

__global__ __launch_bounds__(128, 3)
void rotary_f2(const float* __restrict__ x,
               const float* __restrict__ invf,
               float* __restrict__ out) {
    extern __shared__ __align__(16) char dsm[];
    float2* sc = (float2*)(dsm + SM_SC);

    const int tid  = threadIdx.x;
    const int w    = tid >> 5;
    const int lane = tid & 31;
    const int g    = lane >> 3;     // row group 0..3
    const int h    = lane & 7;      // col group 0..7

    // ---- stage A: 128 rows x 256B, coalesced LDG.128 -> 2x STS.64 k-major ----
    {
        const uint4* xg = (const uint4*)(x + (size_t)blockIdx.x * 128 * 64);
        #pragma unroll
        for (int i = 0; i < 16; i++) {
            const int idx = i * 128 + tid;        // u128 chunk id, 2048 total
            const int row = idx >> 4;
            const int kq  = idx & 15;             // 16B chunk within row
            const uint4 v = xg[idx];
            const u64 lo = ((u64)v.y << 32) | v.x;   // k-pair 2kq
            const u64 hi = ((u64)v.w << 32) | v.z;   // k-pair 2kq+1
            char* base = dsm + SM_A + row * 8;
            *(u64*)(base + (2 * kq)     * A_K_STRIDE) = lo;
            *(u64*)(base + (2 * kq + 1) * A_K_STRIDE) = hi;
        }
    }

    // ---- stage B: copy packed M (2064 u64) ----
    {
        u64* bs = (u64*)(dsm + SM_B);
        #pragma unroll
        for (int i = 0; i < 17; i++) {
            const int idx = tid + 128 * i;
            if (idx < 8 * B_BLK_U64) bs[idx] = g_Bp[idx];
        }
    }

    // ---- sincos table: 8 tokens x 32 freqs ----
    {
        #pragma unroll
        for (int e = 0; e < 2; e++) {
            const int idx = tid * 2 + e;          // 256 entries
            const int t = idx >> 5, m = idx & 31;
            const int pos = (blockIdx.x * 8 + t) & (SEQ - 1);
            float sn, cs;
            sincosf((float)pos * invf[m], &sn, &cs);
            sc[idx] = make_float2(sn, cs);
        }
    }
    __syncthreads();

    // ---- mainloop: 8x8 register tile, fully unrolled (immediate offsets) ----
    const int rowbase = w * 8 + g * 2;
    const char* abase = dsm + SM_A + rowbase * 8;
    const char* bbase = dsm + SM_B + h * (B_BLK_U64 * 8);

    u64 acc[64];
    #pragma unroll
    for (int i = 0; i < 64; i++) acc[i] = 0ull;

    #pragma unroll
    for (int kk = 0; kk < 32; kk++) {
        u64 au[8], bu[8];
        #pragma unroll
        for (int j = 0; j < 4; j++) {
            const ulonglong2 a2 =
                *(const ulonglong2*)(abase + kk * A_K_STRIDE + j * 256);
            au[2 * j] = a2.x;  au[2 * j + 1] = a2.y;
            const ulonglong2 b2 =
                *(const ulonglong2*)(bbase + kk * 64 + j * 16);
            bu[2 * j] = b2.x;  bu[2 * j + 1] = b2.y;
        }
        #pragma unroll
        for (int r = 0; r < 8; r++) {
            #pragma unroll
            for (int c = 0; c < 8; c++) {
                FMA2(acc[r * 8 + c], au[r], bu[c]);
            }
        }
    }

    // ---- epilogue: hsum over k halves, RoPE, *sqrt(1024)=32, STG ----
    #pragma unroll
    for (int r = 0; r < 8; r++) {
        const int row = rowbase + (r & 1) + (r >> 1) * 32;
        const int tok = row >> 4;
        float o1[4], o2[4];
        #pragma unroll
        for (int p = 0; p < 4; p++) {
            const float2 scm = sc[tok * 32 + 4 * h + p];
            const float2 a0 = *(const float2*)&acc[r * 8 + 2 * p];
            const float2 a1 = *(const float2*)&acc[r * 8 + 2 * p + 1];
            const float y1 = a0.x + a0.y;
            const float y2 = a1.x + a1.y;
            o1[p] = (y1 * scm.y - y2 * scm.x) * 32.0f;
            o2[p] = (y1 * scm.x + y2 * scm.y) * 32.0f;
        }
        float* orow = out + ((size_t)blockIdx.x * 128 + row) * 64;
        *(float4*)(orow + 4 * h)      = make_float4(o1[0], o1[1], o1[2], o1[3]);
        *(float4*)(orow + 32 + 4 * h) = make_float4(o2[0], o2[1], o2[2], o2[3]);
    }
}

// ---------------------------------------------------------------------------
extern "C" void kernel_launch(void* const* d_in, const int* in_sizes, int n_in,
                              void* d_out, int out_size) {
    const float* x      = (const float*)d_in[0];
    const float* matrix = (const float*)d_in[1];
    const float* thetas = (const float*)d_in[2];
    const float* tscale = (const float*)d_in[3];
    const float* invf   = (const float*)d_in[4];
    const int*   pairs  = (const int*)d_in[5];
    float* out = (float*)d_out;

    static bool attr_set = false;
    if (!attr_set) {
        cudaFuncSetAttribute(rotary_f2,
                             cudaFuncAttributeMaxDynamicSharedMemorySize,
                             SMEM_DYN);
        attr_set = true;
    }

    const int nrows  = in_sizes[0] / D;      // 524288
    const int blocks = nrows / 128;          // 4096

    build_M_kernel<<<1, 256>>>(matrix, thetas, tscale, pairs);
    rotary_f2<<<blocks, 128, SMEM_DYN>>>(x, invf, out);
}